// round 4
// baseline (speedup 1.0000x reference)
#include <cuda_runtime.h>
#include <cuda_bf16.h>
#include <stdint.h>
#include <math.h>

#define NN 150000
#define EE 2400000
#define BBG 50000
#define HF 128
#define HF2 64

// weight pair offsets (uint32 bf162-pairs, layout [k/2][N] per weight)
#define WOFF1  0
#define WOFF2  8192
#define WOFF3  16384
#define WOFFC1 20480
#define WOFFC2 32768
#define WPAIRS 36864

// classifier intermediate offset in pair buffers (after 50000*96 input pairs)
#define COFF   4800000

// ---------------- scratch (static device globals; no allocation) -------------
__device__ float    g_bufF[(size_t)NN * HF];          // fp32 GEMM outputs (pre-agg)
__device__ uint32_t g_aH[(size_t)NN * HF / 2];        // split activations hi (bf162 pairs)
__device__ uint32_t g_aL[(size_t)NN * HF / 2];        // split activations lo
__device__ uint32_t g_wh[WPAIRS];
__device__ uint32_t g_wl[WPAIRS];
__device__ float g_dinv[NN];
__device__ int   g_deg[NN];
__device__ int   g_rowptr[NN + 1];
__device__ int   g_cursor[NN];
__device__ int   g_colsrc[EE];

// ---------------- helpers ----------------------------------------------------
__device__ __forceinline__ void split2(float x, float y, uint32_t& hi, uint32_t& lo) {
    __nv_bfloat16 hx = __float2bfloat16(x);
    __nv_bfloat16 hy = __float2bfloat16(y);
    float rx = x - __bfloat162float(hx);
    float ry = y - __bfloat162float(hy);
    __nv_bfloat162 h;
    h.x = hx; h.y = hy;
    __nv_bfloat162 l = __floats2bfloat162_rn(rx, ry);
    hi = reinterpret_cast<uint32_t&>(h);
    lo = reinterpret_cast<uint32_t&>(l);
}

__device__ __forceinline__ void mma16816(float c[4], const uint32_t a[4], const uint32_t b[2]) {
    asm volatile(
        "mma.sync.aligned.m16n8k16.row.col.f32.bf16.bf16.f32 "
        "{%0,%1,%2,%3}, {%4,%5,%6,%7}, {%8,%9}, {%0,%1,%2,%3};"
        : "+f"(c[0]), "+f"(c[1]), "+f"(c[2]), "+f"(c[3])
        : "r"(a[0]), "r"(a[1]), "r"(a[2]), "r"(a[3]), "r"(b[0]), "r"(b[1]));
}

// ---------------- setup kernels ---------------------------------------------
__global__ void k_zero_deg() {
    int i = blockIdx.x * blockDim.x + threadIdx.x;
    if (i < NN) g_deg[i] = 0;
}

__global__ void k_count(const int* __restrict__ ei) {
    int e = blockIdx.x * blockDim.x + threadIdx.x;
    if (e < EE) atomicAdd(&g_deg[ei[EE + e]], 1);
}

__global__ void k_scan() {
    __shared__ int s[1024];
    const int t = threadIdx.x;
    const int chunk = (NN + 1023) / 1024;
    const int start = t * chunk;
    const int end = min(start + chunk, NN);
    int sum = 0;
    for (int i = start; i < end; i++) sum += g_deg[i];
    s[t] = sum;
    __syncthreads();
    for (int off = 1; off < 1024; off <<= 1) {
        int v = (t >= off) ? s[t - off] : 0;
        __syncthreads();
        s[t] += v;
        __syncthreads();
    }
    if (t == 0) g_rowptr[NN] = s[1023];
    int base = (t == 0) ? 0 : s[t - 1];
    for (int i = start; i < end; i++) {
        g_rowptr[i] = base;
        g_cursor[i] = base;
        int d = g_deg[i];
        base += d;
        g_dinv[i] = rsqrtf((float)(d + 1));
    }
}

__global__ void k_scatter(const int* __restrict__ ei) {
    int e = blockIdx.x * blockDim.x + threadIdx.x;
    if (e < EE) {
        int srcn = ei[e];
        int dstn = ei[EE + e];
        int pos = atomicAdd(&g_cursor[dstn], 1);
        g_colsrc[pos] = srcn;
    }
}

// split all weights once into (k/2, N) bf162-pair layout
__global__ void k_split_w(const float* __restrict__ W1, const float* __restrict__ W2,
                          const float* __restrict__ W3, const float* __restrict__ Wc1,
                          const float* __restrict__ Wc2) {
    int p = blockIdx.x * blockDim.x + threadIdx.x;
    if (p >= WPAIRS) return;
    const float* src;
    int off, N;
    if (p < WOFF2)       { src = W1;  off = p - WOFF1;  N = 128; }
    else if (p < WOFF3)  { src = W2;  off = p - WOFF2;  N = 128; }
    else if (p < WOFFC1) { src = W3;  off = p - WOFF3;  N = 64;  }
    else if (p < WOFFC2) { src = Wc1; off = p - WOFFC1; N = 128; }
    else                 { src = Wc2; off = p - WOFFC2; N = 64;  }
    int pr = off / N, n = off % N;
    float a = src[(size_t)(2 * pr) * N + n];
    float b = src[(size_t)(2 * pr + 1) * N + n];
    uint32_t h, l;
    split2(a, b, h, l);
    g_wh[p] = h;
    g_wl[p] = l;
}

// split input x once
__global__ void k_split_x(const float* __restrict__ x) {
    int i = blockIdx.x * blockDim.x + threadIdx.x;   // per 4 elements (2 pairs)
    if (i >= NN * HF / 4) return;
    float4 v = ((const float4*)x)[i];
    uint32_t h0, l0, h1, l1;
    split2(v.x, v.y, h0, l0);
    split2(v.z, v.w, h1, l1);
    ((uint2*)g_aH)[i] = make_uint2(h0, h1);
    ((uint2*)g_aL)[i] = make_uint2(l0, l1);
}

// ---------------- bf16 split-MMA GEMM (pre-split inputs) ---------------------
// C[M,N] = A[M,K] @ W[K,N]. A given as hi/lo bf162-pair arrays (row stride K/2).
// W pre-split in g_wh/g_wl at wOff. 3 mma products. Block 128x64, 8 warps.

#define BM 128
#define BN 64
#define SA 20   // As pair-stride (uint32 units)
#define SB 72   // Bs pair-row stride

template <bool FUSE, bool OUTSPLIT>
__global__ void __launch_bounds__(256)
k_mma(const uint32_t* __restrict__ Ah, const uint32_t* __restrict__ Al,
      int wOff, const float* __restrict__ bias,
      float* __restrict__ Cf, uint32_t* __restrict__ OutH, uint32_t* __restrict__ OutL,
      int M, int K, int N) {
    __shared__ uint32_t sAh[BM * SA];
    __shared__ uint32_t sAl[BM * SA];
    __shared__ uint32_t sBh[16 * SB];
    __shared__ uint32_t sBl[16 * SB];

    const int tid = threadIdx.x;
    const int wid = tid >> 5;
    const int lane = tid & 31;
    const int wm = wid & 3;
    const int wn = wid >> 2;
    const int gid = lane >> 2;
    const int tig = lane & 3;
    const int bm = blockIdx.y * BM;
    const int bn = blockIdx.x * BN;
    const int Kp = K >> 1;

    float c[8][4];
#pragma unroll
    for (int i = 0; i < 8; i++)
#pragma unroll
        for (int j = 0; j < 4; j++) c[i][j] = 0.f;

    const int bpr = tid >> 4;           // B pair-row 0..15
    const int bn4 = (tid & 15) * 4;     // B col group

    for (int k0p = 0; k0p < Kp; k0p += 16) {
        // --- A tile: 128 rows x 16 pairs, hi+lo, uint4 copies ---
#pragma unroll
        for (int i = 0; i < 2; i++) {
            int task = tid + i * 256;   // 0..511
            int row = task >> 2;
            int qg = task & 3;
            int gr = bm + row;
            uint4 vh = make_uint4(0u, 0u, 0u, 0u);
            uint4 vl = make_uint4(0u, 0u, 0u, 0u);
            if (gr < M) {
                const uint4* ph = (const uint4*)&Ah[(size_t)gr * Kp + k0p];
                const uint4* pl = (const uint4*)&Al[(size_t)gr * Kp + k0p];
                vh = ph[qg];
                vl = pl[qg];
            }
            *(uint4*)&sAh[row * SA + qg * 4] = vh;
            *(uint4*)&sAl[row * SA + qg * 4] = vl;
        }
        // --- B tile: 16 pair-rows x 64 cols, direct copies ---
        {
            size_t gidx = (size_t)wOff + (size_t)(k0p + bpr) * N + bn + bn4;
            *(uint4*)&sBh[bpr * SB + bn4] = *(const uint4*)&g_wh[gidx];
            *(uint4*)&sBl[bpr * SB + bn4] = *(const uint4*)&g_wl[gidx];
        }
        __syncthreads();

#pragma unroll
        for (int ks = 0; ks < 2; ks++) {
            const int p0 = ks * 8;
            uint32_t ah[2][4], al[2][4];
#pragma unroll
            for (int mt = 0; mt < 2; mt++) {
                int r = wm * 32 + mt * 16 + gid;
                int b0 = r * SA + p0 + tig;
                ah[mt][0] = sAh[b0];
                ah[mt][1] = sAh[b0 + 8 * SA];
                ah[mt][2] = sAh[b0 + 4];
                ah[mt][3] = sAh[b0 + 8 * SA + 4];
                al[mt][0] = sAl[b0];
                al[mt][1] = sAl[b0 + 8 * SA];
                al[mt][2] = sAl[b0 + 4];
                al[mt][3] = sAl[b0 + 8 * SA + 4];
            }
            uint32_t bh[4][2], bl[4][2];
#pragma unroll
            for (int nt = 0; nt < 4; nt++) {
                int cc = wn * 32 + nt * 8 + gid;
                bh[nt][0] = sBh[(p0 + tig) * SB + cc];
                bh[nt][1] = sBh[(p0 + tig + 4) * SB + cc];
                bl[nt][0] = sBl[(p0 + tig) * SB + cc];
                bl[nt][1] = sBl[(p0 + tig + 4) * SB + cc];
            }
#pragma unroll
            for (int mt = 0; mt < 2; mt++)
#pragma unroll
                for (int nt = 0; nt < 4; nt++) {
                    int t = mt * 4 + nt;
                    mma16816(c[t], ah[mt], bh[nt]);
                    mma16816(c[t], ah[mt], bl[nt]);
                    mma16816(c[t], al[mt], bh[nt]);
                }
        }
        __syncthreads();
    }

    // --- epilogue ---
#pragma unroll
    for (int mt = 0; mt < 2; mt++)
#pragma unroll
        for (int nt = 0; nt < 4; nt++) {
            int t = mt * 4 + nt;
            int gr0 = bm + wm * 32 + mt * 16 + gid;
            int gc = bn + wn * 32 + nt * 8 + tig * 2;
            float v0 = c[t][0], v1 = c[t][1], v2 = c[t][2], v3 = c[t][3];
            if (FUSE) {
                float b0 = bias[gc], b1 = bias[gc + 1];
                v0 = fmaxf(v0 + b0, 0.f);
                v1 = fmaxf(v1 + b1, 0.f);
                v2 = fmaxf(v2 + b0, 0.f);
                v3 = fmaxf(v3 + b1, 0.f);
            }
            if (OUTSPLIT) {
                uint32_t h, l;
                if (gr0 < M) {
                    split2(v0, v1, h, l);
                    size_t p = (size_t)gr0 * (N >> 1) + (gc >> 1);
                    OutH[p] = h;
                    OutL[p] = l;
                }
                if (gr0 + 8 < M) {
                    split2(v2, v3, h, l);
                    size_t p = (size_t)(gr0 + 8) * (N >> 1) + (gc >> 1);
                    OutH[p] = h;
                    OutL[p] = l;
                }
            } else {
                if (gr0 < M) *(float2*)&Cf[(size_t)gr0 * N + gc] = make_float2(v0, v1);
                if (gr0 + 8 < M) *(float2*)&Cf[(size_t)(gr0 + 8) * N + gc] = make_float2(v2, v3);
            }
        }
}

// ---------------- gather aggregation, split-bf16 output ----------------------
template <int F>
__global__ void k_agg(const float* __restrict__ h, const float* __restrict__ bias,
                      uint32_t* __restrict__ outH, uint32_t* __restrict__ outL) {
    int warp = (blockIdx.x * blockDim.x + threadIdx.x) >> 5;
    int lane = threadIdx.x & 31;
    if (warp >= NN) return;
    const int VPL = F / 32;
    float di = g_dinv[warp];
    float di2 = di * di;
    float acc[VPL];
    const float* hrow = h + (size_t)warp * F + lane * VPL;
    if (VPL == 4) {
        float4 v = *(const float4*)hrow;
        acc[0] = v.x * di2; acc[1] = v.y * di2; acc[2] = v.z * di2; acc[3] = v.w * di2;
    } else {
        float2 v = *(const float2*)hrow;
        acc[0] = v.x * di2; acc[1] = v.y * di2;
    }
    int beg = g_rowptr[warp];
    int end = g_rowptr[warp + 1];
    for (int j = beg; j < end; j++) {
        int s = g_colsrc[j];
        float w = g_dinv[s] * di;
        const float* hs = h + (size_t)s * F + lane * VPL;
        if (VPL == 4) {
            float4 v = *(const float4*)hs;
            acc[0] += v.x * w; acc[1] += v.y * w; acc[2] += v.z * w; acc[3] += v.w * w;
        } else {
            float2 v = *(const float2*)hs;
            acc[0] += v.x * w; acc[1] += v.y * w;
        }
    }
    if (VPL == 4) {
        float4 b = *(const float4*)&bias[lane * 4];
        float o0 = fmaxf(acc[0] + b.x, 0.f);
        float o1 = fmaxf(acc[1] + b.y, 0.f);
        float o2 = fmaxf(acc[2] + b.z, 0.f);
        float o3 = fmaxf(acc[3] + b.w, 0.f);
        uint32_t h0, l0, h1, l1;
        split2(o0, o1, h0, l0);
        split2(o2, o3, h1, l1);
        size_t p = (size_t)warp * (F / 2) + lane * 2;
        *(uint2*)&outH[p] = make_uint2(h0, h1);
        *(uint2*)&outL[p] = make_uint2(l0, l1);
    } else {
        float2 b = *(const float2*)&bias[lane * 2];
        float o0 = fmaxf(acc[0] + b.x, 0.f);
        float o1 = fmaxf(acc[1] + b.y, 0.f);
        uint32_t h0, l0;
        split2(o0, o1, h0, l0);
        size_t p = (size_t)warp * (F / 2) + lane;
        outH[p] = h0;
        outL[p] = l0;
    }
}

// ---------------- final 64->2 + log_softmax ----------------------------------
__global__ void k_final(const float* __restrict__ z, const float* __restrict__ Wc3,
                        const float* __restrict__ bc3, float* __restrict__ out) {
    __shared__ float sw[HF2 * 2];
    __shared__ float sb[2];
    if (threadIdx.x < HF2 * 2) sw[threadIdx.x] = Wc3[threadIdx.x];
    if (threadIdx.x < 2) sb[threadIdx.x] = bc3[threadIdx.x];
    __syncthreads();
    int g = blockIdx.x * blockDim.x + threadIdx.x;
    if (g >= BBG) return;
    const float* zr = z + (size_t)g * HF2;
    float a0 = sb[0], a1 = sb[1];
#pragma unroll
    for (int k = 0; k < HF2; k++) {
        float zv = zr[k];
        a0 += zv * sw[2 * k + 0];
        a1 += zv * sw[2 * k + 1];
    }
    float m = fmaxf(a0, a1);
    float l = logf(expf(a0 - m) + expf(a1 - m));
    out[2 * g + 0] = a0 - m - l;
    out[2 * g + 1] = a1 - m - l;
}

// ---------------- launch -----------------------------------------------------
extern "C" void kernel_launch(void* const* d_in, const int* in_sizes, int n_in,
                              void* d_out, int out_size) {
    const float* x   = (const float*)d_in[0];
    const int*   ei  = (const int*)d_in[1];
    const float* W1  = (const float*)d_in[2];
    const float* b1  = (const float*)d_in[3];
    const float* W2  = (const float*)d_in[4];
    const float* b2  = (const float*)d_in[5];
    const float* W3  = (const float*)d_in[6];
    const float* b3  = (const float*)d_in[7];
    const float* Wc1 = (const float*)d_in[8];
    const float* bc1 = (const float*)d_in[9];
    const float* Wc2 = (const float*)d_in[10];
    const float* bc2 = (const float*)d_in[11];
    const float* Wc3 = (const float*)d_in[12];
    const float* bc3 = (const float*)d_in[13];
    float* out = (float*)d_out;

    float* bufF;
    uint32_t* aH;
    uint32_t* aL;
    cudaGetSymbolAddress((void**)&bufF, g_bufF);
    cudaGetSymbolAddress((void**)&aH, g_aH);
    cudaGetSymbolAddress((void**)&aL, g_aL);

    // --- preprocessing ---
    k_zero_deg<<<(NN + 255) / 256, 256>>>();
    k_count<<<(EE + 255) / 256, 256>>>(ei);
    k_scan<<<1, 1024>>>();
    k_scatter<<<(EE + 255) / 256, 256>>>(ei);
    k_split_w<<<(WPAIRS + 255) / 256, 256>>>(W1, W2, W3, Wc1, Wc2);
    k_split_x<<<(NN * HF / 4 + 255) / 256, 256>>>(x);

    const int aggBlocks = (NN * 32 + 255) / 256;
    const int mRows = (NN + BM - 1) / BM;
    const int cRows = (BBG + BM - 1) / BM;
    dim3 g1(HF / BN, mRows);
    dim3 g3(HF2 / BN, mRows);
    dim3 gc1(HF / BN, cRows);
    dim3 gc2(HF2 / BN, cRows);

    // layer 1
    k_mma<false, false><<<g1, 256>>>(aH, aL, WOFF1, nullptr, bufF, nullptr, nullptr, NN, HF, HF);
    k_agg<HF><<<aggBlocks, 256>>>(bufF, b1, aH, aL);
    // layer 2
    k_mma<false, false><<<g1, 256>>>(aH, aL, WOFF2, nullptr, bufF, nullptr, nullptr, NN, HF, HF);
    k_agg<HF><<<aggBlocks, 256>>>(bufF, b2, aH, aL);
    // layer 3 (128 -> 64)
    k_mma<false, false><<<g3, 256>>>(aH, aL, WOFF3, nullptr, bufF, nullptr, nullptr, NN, HF, HF2);
    k_agg<HF2><<<aggBlocks, 256>>>(bufF, b3, aH, aL);
    // classifier: input viewed as [50000, 192] (96 pairs/row)
    k_mma<true, true><<<gc1, 256>>>(aH, aL, WOFFC1, bc1, nullptr, aH + COFF, aL + COFF,
                                    BBG, 3 * HF2, HF);
    k_mma<true, false><<<gc2, 256>>>(aH + COFF, aL + COFF, WOFFC2, bc2, bufF, nullptr, nullptr,
                                     BBG, HF, HF2);
    // final 64->2 + log_softmax
    k_final<<<(BBG + 255) / 256, 256>>>(bufF, Wc3, bc3, out);
}